// round 14
// baseline (speedup 1.0000x reference)
#include <cuda_runtime.h>
#include <math.h>

// ---------------------------------------------------------------------------
// Matern kernel matrix, single fused kernel.
// 64x128 tiles -> grid = 128 blocks = exactly ONE wave on 148 SMs (grid=256
// was 2 waves with a 40-SM idle tail). 256 threads, 4x8 micro-tile per thread
// (32 elems): crossbar 0.375 LDS.128/elem, dot phase bound by the FMA pipe.
// Per-block 257-entry table L(x)=log2(C x^nu K_nu(x)) over x in [0,48]
// (one entry per thread, 32-pt trapezoid of the reference's integral),
// built overlapping the tile-load LDG latency. Tiles pre-scaled by fac/du so
// sqrt.approx yields the table coordinate directly.
// ---------------------------------------------------------------------------

#define NQ2 32
#define HQ2 (6.0f / (NQ2 - 1))
#define DU     (48.0f / 256.0f)
#define INV_DU (256.0f / 48.0f)
#define LOG2E 1.44269504088896340736f

__device__ __forceinline__ float ex2f(float x) {
    float r; asm("ex2.approx.ftz.f32 %0, %1;" : "=f"(r) : "f"(x)); return r;
}
__device__ __forceinline__ float lg2f(float x) {
    float r; asm("lg2.approx.f32 %0, %1;" : "=f"(r) : "f"(x)); return r;
}
__device__ __forceinline__ float sqrt_approx(float x) {
    float r; asm("sqrt.approx.ftz.f32 %0, %1;" : "=f"(r) : "f"(x)); return r;
}

__global__ __launch_bounds__(256) void matern_fused(const float* __restrict__ X,
                                                    const float* __restrict__ nu_p,
                                                    const float* __restrict__ lv_p,
                                                    const float* __restrict__ ll_p,
                                                    float* __restrict__ out,
                                                    int N) {
    __shared__ float sxi[64][36];
    __shared__ float sxj[128][36];
    __shared__ float sni[64], snj[128];
    __shared__ float s_a[NQ2];     // (cosh t_q - 1) * log2(e)
    __shared__ float s_c[NQ2];     // w_q * cosh(nu t_q)
    __shared__ float stbl[257];    // L(k * DU)
    __shared__ float s_scale, s_var, s_log2C, s_nu;

    const int tid = threadIdx.x;
    const int tx = tid & 15, ty = tid >> 4;
    const int i0 = blockIdx.y * 64, j0 = blockIdx.x * 128;

    // issue tile LDGs early (latency overlapped with coefficient/scalar math)
    const float4* Xi = (const float4*)(X + i0 * 32);   // 512 float4
    const float4* Xj = (const float4*)(X + j0 * 32);   // 1024 float4
    float4 vi[2], vj[4];
#pragma unroll
    for (int m = 0; m < 2; m++) vi[m] = Xi[m * 256 + tid];
#pragma unroll
    for (int m = 0; m < 4; m++) vj[m] = Xj[m * 256 + tid];

    // quadrature coefficients + scalar constants
    if (tid < NQ2) {
        float nu = nu_p[0];
        float t  = HQ2 * (float)tid;
        s_a[tid] = (coshf(t) - 1.f) * LOG2E;
        float w  = (tid == 0 || tid == NQ2 - 1) ? 0.5f * HQ2 : HQ2;
        s_c[tid] = w * coshf(nu * t);
    } else if (tid == 32) {
        float nu = nu_p[0], lv = lv_p[0], ll = ll_p[0];
        s_scale = sqrtf(2.f * nu) * __expf(-ll) * INV_DU;
        s_var   = __expf(lv);
        s_log2C = lv * LOG2E + (1.f - nu) - lgammaf(nu) * LOG2E;
        s_nu    = nu;
    }
    __syncthreads();

    const float scale = s_scale;
    const int kch = tid & 7;       // 8 lanes per row

    // tiles (prescaled) + fused norm reduction
#pragma unroll
    for (int m = 0; m < 2; m++) {
        int idx = m * 256 + tid;
        int r = idx >> 3;
        float4 v = vi[m];
        v.x *= scale; v.y *= scale; v.z *= scale; v.w *= scale;
        *(float4*)&sxi[r][4 * kch] = v;
        float p = fmaf(v.x, v.x, fmaf(v.y, v.y, fmaf(v.z, v.z, v.w * v.w)));
        p += __shfl_xor_sync(0xffffffffu, p, 1);
        p += __shfl_xor_sync(0xffffffffu, p, 2);
        p += __shfl_xor_sync(0xffffffffu, p, 4);
        if (kch == 0) sni[r] = p;
    }
#pragma unroll
    for (int m = 0; m < 4; m++) {
        int idx = m * 256 + tid;
        int r = idx >> 3;
        float4 v = vj[m];
        v.x *= scale; v.y *= scale; v.z *= scale; v.w *= scale;
        *(float4*)&sxj[r][4 * kch] = v;
        float p = fmaf(v.x, v.x, fmaf(v.y, v.y, fmaf(v.z, v.z, v.w * v.w)));
        p += __shfl_xor_sync(0xffffffffu, p, 1);
        p += __shfl_xor_sync(0xffffffffu, p, 2);
        p += __shfl_xor_sync(0xffffffffu, p, 4);
        if (kch == 0) snj[r] = p;
    }

    // per-thread table entry: L(x_k), k = tid (entry 256 never read: u<=254.99)
    {
        const float x = DU * (float)tid;
        float S = 0.f;
#pragma unroll
        for (int q = 0; q < NQ2; q++) {
            S = fmaf(s_c[q], ex2f(-x * s_a[q]), S);
        }
        float L = s_log2C + s_nu * lg2f(x) - x * LOG2E + lg2f(S);
        stbl[tid] = fmaxf(L, -150.f);
    }
    __syncthreads();

    // 4x8 micro-tile dot: rows i = ty*4 + r, cols j = tx + 16*c (c = 0..7)
    float acc[4][8];
#pragma unroll
    for (int r = 0; r < 4; r++)
#pragma unroll
        for (int c = 0; c < 8; c++) acc[r][c] = 0.f;

#pragma unroll
    for (int kc = 0; kc < 8; kc++) {
        float4 a[4], b[8];
#pragma unroll
        for (int r = 0; r < 4; r++) a[r] = *(const float4*)&sxi[ty * 4 + r][kc * 4];
#pragma unroll
        for (int c = 0; c < 8; c++) b[c] = *(const float4*)&sxj[tx + 16 * c][kc * 4];
#pragma unroll
        for (int r = 0; r < 4; r++)
#pragma unroll
            for (int c = 0; c < 8; c++) {
                acc[r][c] = fmaf(a[r].x, b[c].x, acc[r][c]);
                acc[r][c] = fmaf(a[r].y, b[c].y, acc[r][c]);
                acc[r][c] = fmaf(a[r].z, b[c].z, acc[r][c]);
                acc[r][c] = fmaf(a[r].w, b[c].w, acc[r][c]);
            }
    }

    const float var_s = s_var;
    float ni[4], nj[8];
#pragma unroll
    for (int r = 0; r < 4; r++) ni[r] = sni[ty * 4 + r];
#pragma unroll
    for (int c = 0; c < 8; c++) nj[c] = snj[tx + 16 * c];

    const int d0 = i0 - j0;
    const bool diagblk = (d0 >= 0) && (d0 < 128);

#pragma unroll
    for (int r = 0; r < 4; r++) {
        const int i = i0 + ty * 4 + r;
#pragma unroll
        for (int c = 0; c < 8; c++) {
            const int j = j0 + tx + 16 * c;
            float sq = fmaxf(fmaf(-2.f, acc[r][c], ni[r] + nj[c]), 0.f);
            float u  = fminf(sqrt_approx(sq), 254.99f);
            int   kk = (int)u;
            float f  = u - (float)kk;
            float L0 = stbl[kk], L1 = stbl[kk + 1];
            float val = ex2f(fmaf(f, L1 - L0, L0));
            if (diagblk && i == j) val = var_s;
            out[i * N + j] = val;
        }
    }
}

extern "C" void kernel_launch(void* const* d_in, const int* in_sizes, int n_in,
                              void* d_out, int out_size) {
    const float* X  = (const float*)d_in[0];
    const float* nu = (const float*)d_in[1];
    const float* lv = (const float*)d_in[2];
    const float* ll = (const float*)d_in[3];
    float* out = (float*)d_out;
    const int N = in_sizes[0] / 32;   // 1024

    dim3 grid(N / 128, N / 64), block(256);
    matern_fused<<<grid, block>>>(X, nu, lv, ll, out, N);
}